// round 12
// baseline (speedup 1.0000x reference)
#include <cuda_runtime.h>
#include <cuda_bf16.h>
#include <cuda_fp16.h>
#include <math.h>
#include <stdint.h>

// Problem constants
#define NN    50000
#define EE    800000
#define IN_F  512
#define HID   256
#define OUT_F 64

// ---------------- scratch (static device globals; no allocs) ----------------
__device__ __half g_xw1h[(size_t)NN * HID];   // X @ W1 (fp16 gather table)
__device__ __half g_hw2h[(size_t)NN * OUT_F]; // h @ W2 (fp16 gather table)
__device__ int   g_rowptr[NN + 1];
__device__ int   g_is64;
__device__ __nv_bfloat16 g_w1t_hi[(size_t)HID * IN_F]; // W1^T bf16 hi [256,512]
__device__ __nv_bfloat16 g_w1t_lo[(size_t)HID * IN_F]; // W1^T bf16 lo
__device__ __nv_bfloat16 g_h_hi[(size_t)NN * HID];     // h split hi [50000,256]
__device__ __nv_bfloat16 g_h_lo[(size_t)NN * HID];     // h split lo
__device__ __nv_bfloat16 g_w2t_hi[(size_t)OUT_F * HID]; // W2^T bf16 hi [64,256]
__device__ __nv_bfloat16 g_w2t_lo[(size_t)OUT_F * HID]; // W2^T bf16 lo

// ======================= PTX helpers ========================================
__device__ __forceinline__ uint32_t smem_u32(const void* p) {
    uint32_t a;
    asm("{ .reg .u64 t; cvta.to.shared.u64 t, %1; cvt.u32.u64 %0, t; }"
        : "=r"(a) : "l"(p));
    return a;
}
__device__ __forceinline__ void cpa16(uint32_t dst, const void* src) {
    asm volatile("cp.async.cg.shared.global [%0], [%1], 16;"
                 :: "r"(dst), "l"(src) : "memory");
}
#define CP_COMMIT()  asm volatile("cp.async.commit_group;" ::: "memory")
#define CP_WAIT_2()  asm volatile("cp.async.wait_group 2;" ::: "memory")
#define CP_WAIT_1()  asm volatile("cp.async.wait_group 1;" ::: "memory")
#define CP_WAIT_0()  asm volatile("cp.async.wait_group 0;" ::: "memory")

__device__ __forceinline__ void ldsm_x4(uint32_t& r0, uint32_t& r1,
                                        uint32_t& r2, uint32_t& r3, uint32_t addr) {
    asm volatile("ldmatrix.sync.aligned.m8n8.x4.shared.b16 {%0,%1,%2,%3}, [%4];"
                 : "=r"(r0), "=r"(r1), "=r"(r2), "=r"(r3) : "r"(addr));
}
__device__ __forceinline__ void mma_bf16_2(float* c, const uint32_t* a,
                                           uint32_t b0, uint32_t b1) {
    asm volatile(
        "mma.sync.aligned.m16n8k16.row.col.f32.bf16.bf16.f32 "
        "{%0,%1,%2,%3}, {%4,%5,%6,%7}, {%8,%9}, {%0,%1,%2,%3};"
        : "+f"(c[0]), "+f"(c[1]), "+f"(c[2]), "+f"(c[3])
        : "r"(a[0]), "r"(a[1]), "r"(a[2]), "r"(a[3]), "r"(b0), "r"(b1));
}
__device__ __forceinline__ uint32_t bf2_pack(float a, float b) {
    __nv_bfloat162 t = __floats2bfloat162_rn(a, b);
    return *reinterpret_cast<uint32_t*>(&t);
}
__device__ __forceinline__ float bf_round(float x) {
    return __bfloat162float(__float2bfloat16_rn(x));
}
__device__ __forceinline__ uint32_t h2_pack(float a, float b) {
    __half2 t = __floats2half2_rn(a, b);
    return *reinterpret_cast<uint32_t*>(&t);
}

// ---------------- index dtype detection (int64 vs int32) --------------------
__global__ void detect_idx_kernel(const void* __restrict__ a_col_raw, int E) {
    if (threadIdx.x != 0 || blockIdx.x != 0) return;
    const long long* p = (const long long*)a_col_raw;
    int ok = 1;
    for (int i = 0; i < 16; i++) {
        long long v = p[i];
        if (v < 0 || v >= NN) { ok = 0; break; }
    }
    if (ok) {
        for (int i = 0; i < 16; i++) {
            long long v = p[E / 2 + i];
            if (v < 0 || v >= NN) { ok = 0; break; }
        }
    }
    g_is64 = ok;
}
__device__ __forceinline__ int load_idx(const void* p, int i, int is64) {
    if (is64) return (int)((const long long*)p)[i];
    return ((const int*)p)[i];
}

// ---------------- merged weight prep (bf16 hi/lo) ----------------------------
__global__ void prep_w_kernel(const float* __restrict__ W1,
                              const float* __restrict__ W2) {
    int idx = blockIdx.x * blockDim.x + threadIdx.x;
    if (idx < IN_F * HID) {
        int n = idx >> 9, k = idx & 511;
        float v = W1[(size_t)k * HID + n];
        __nv_bfloat16 h = __float2bfloat16_rn(v);
        g_w1t_hi[idx] = h;
        g_w1t_lo[idx] = __float2bfloat16_rn(v - __bfloat162float(h));
    } else {
        int j = idx - IN_F * HID;
        if (j < HID * OUT_F) {
            int n = j >> 8, k = j & 255;
            float v = W2[(size_t)k * OUT_F + n];
            __nv_bfloat16 h = __float2bfloat16_rn(v);
            g_w2t_hi[j] = h;
            g_w2t_lo[j] = __float2bfloat16_rn(v - __bfloat162float(h));
        }
    }
}

// ---------------- rowptr ----------------------------------------------------
__global__ void build_rowptr_kernel(const void* __restrict__ a_row, int E) {
    int r = blockIdx.x * blockDim.x + threadIdx.x;
    if (r > NN) return;
    if (r == NN) { g_rowptr[NN] = E; return; }
    const int is64 = g_is64;
    int lo = 0, hi = E;
    while (lo < hi) {
        int mid = (lo + hi) >> 1;
        if (load_idx(a_row, mid, is64) < r) lo = mid + 1; else hi = mid;
    }
    g_rowptr[r] = lo;
}

// ---------------- GEMM1: X@W1 CTA 128x128, bf16 3-term, A-direct regs -------
// A fragments LDG'd straight from gmem fp32 -> bf16 hi/lo in regs (no A smem).
// B: cp.async 4-deep circular smem, ONE __syncthreads per k-chunk.
#define ROWB    80
#define G1_BSTG 20480               // per-stage: BHI 10240 + BLO 10240
#define G1_TOTAL (4 * G1_BSTG)      // 81920 -> 2 CTAs/SM

__global__ void __launch_bounds__(256, 2)
gemm1_mma_kernel(const float* __restrict__ X, __half* __restrict__ outh) {
    extern __shared__ char smem[];
    const uint32_t sm0 = smem_u32(smem);
    const int tid = threadIdx.x;
    const int wid = tid >> 5, lane = tid & 31;
    const int warp_m = wid & 3, warp_n = wid >> 2;
    const int colBase = blockIdx.x * 128;   // 0 or 128 (HID)
    const int rowBase = blockIdx.y * 128;

    float acc[2][8][4];
    #pragma unroll
    for (int i = 0; i < 2; i++)
        #pragma unroll
        for (int j = 0; j < 8; j++)
            #pragma unroll
            for (int t = 0; t < 4; t++) acc[i][j][t] = 0.f;

    float2 av[2][2][4];   // [mb][ks][frag] fp32 pairs (32 regs)

    auto ldg_a = [&](int kc) {
        int k0 = kc * 32;
        #pragma unroll
        for (int mb = 0; mb < 2; mb++) {
            int r0 = rowBase + warp_m * 32 + mb * 16 + (lane >> 2);
            int r1 = r0 + 8;
            if (r0 >= NN) r0 = NN - 1;
            if (r1 >= NN) r1 = NN - 1;
            const float* p0 = X + (size_t)r0 * IN_F;
            const float* p1 = X + (size_t)r1 * IN_F;
            #pragma unroll
            for (int ks = 0; ks < 2; ks++) {
                int c0 = k0 + ks * 16 + (lane & 3) * 2;
                av[mb][ks][0] = __ldg((const float2*)(p0 + c0));
                av[mb][ks][1] = __ldg((const float2*)(p1 + c0));
                av[mb][ks][2] = __ldg((const float2*)(p0 + c0 + 8));
                av[mb][ks][3] = __ldg((const float2*)(p1 + c0 + 8));
            }
        }
    };

    auto cp_b = [&](int kc) {
        int k0 = kc * 32;
        uint32_t bh = sm0 + (kc & 3) * G1_BSTG;
        uint32_t bl = bh + 10240;
        #pragma unroll
        for (int i = 0; i < 2; i++) {
            int c = tid + 256 * i;          // 0..511 : 128 B-rows x 4 chunks
            int row = c >> 2, q = c & 3;
            uint32_t o = row * ROWB + q * 16;
            cpa16(bh + o, g_w1t_hi + (size_t)(colBase + row) * IN_F + k0 + q * 8);
            cpa16(bl + o, g_w1t_lo + (size_t)(colBase + row) * IN_F + k0 + q * 8);
        }
    };

    const int lq = lane >> 3, lr = lane & 7;

    auto compute_stage = [&](int kc) {
        uint32_t bhb = sm0 + (kc & 3) * G1_BSTG;
        uint32_t blb = bhb + 10240;
        #pragma unroll
        for (int ks = 0; ks < 2; ks++) {
            // convert this ks's A fragments fp32 -> bf16 hi/lo
            uint32_t ahi[2][4], alo[2][4];
            #pragma unroll
            for (int mb = 0; mb < 2; mb++)
                #pragma unroll
                for (int j = 0; j < 4; j++) {
                    float2 v = av[mb][ks][j];
                    float h0 = bf_round(v.x), h1 = bf_round(v.y);
                    ahi[mb][j] = bf2_pack(v.x, v.y);
                    alo[mb][j] = bf2_pack(v.x - h0, v.y - h1);
                }
            #pragma unroll
            for (int g = 0; g < 4; g++) {
                int row = warp_n * 64 + g * 16 + (lq >> 1) * 8 + lr;
                int kb  = ks * 32 + (lq & 1) * 16;
                uint32_t o = row * ROWB + kb;
                uint32_t bh0, bh1, bh2, bh3, bl0, bl1, bl2, bl3;
                ldsm_x4(bh0, bh1, bh2, bh3, bhb + o);
                ldsm_x4(bl0, bl1, bl2, bl3, blb + o);
                #pragma unroll
                for (int mb = 0; mb < 2; mb++) {
                    mma_bf16_2(acc[mb][2*g],   ahi[mb], bh0, bh1);
                    mma_bf16_2(acc[mb][2*g],   ahi[mb], bl0, bl1);
                    mma_bf16_2(acc[mb][2*g],   alo[mb], bh0, bh1);
                    mma_bf16_2(acc[mb][2*g+1], ahi[mb], bh2, bh3);
                    mma_bf16_2(acc[mb][2*g+1], ahi[mb], bl2, bl3);
                    mma_bf16_2(acc[mb][2*g+1], alo[mb], bh2, bh3);
                }
            }
        }
    };

    // prologue: B stages 0..2 in flight
    cp_b(0); CP_COMMIT();
    cp_b(1); CP_COMMIT();
    cp_b(2); CP_COMMIT();

    for (int kc = 0; kc < 16; kc++) {
        ldg_a(kc);                       // private regs; latency hidden by wait+sync
        if (kc <= 13) CP_WAIT_2();
        else if (kc == 14) CP_WAIT_1();
        else CP_WAIT_0();
        __syncthreads();                 // publish B(kc) from all threads
        compute_stage(kc);
        if (kc + 3 < 16) { cp_b(kc + 3); CP_COMMIT(); }
    }

    const int gid = lane >> 2, tg = lane & 3;
    #pragma unroll
    for (int mb = 0; mb < 2; mb++) {
        int r0 = rowBase + warp_m * 32 + mb * 16 + gid;
        int r1 = r0 + 8;
        #pragma unroll
        for (int nb = 0; nb < 8; nb++) {
            int col = colBase + warp_n * 64 + nb * 8 + tg * 2;
            if (r0 < NN)
                *(__half2*)&outh[(size_t)r0 * HID + col] =
                    __floats2half2_rn(acc[mb][nb][0], acc[mb][nb][1]);
            if (r1 < NN)
                *(__half2*)&outh[(size_t)r1 * HID + col] =
                    __floats2half2_rn(acc[mb][nb][2], acc[mb][nb][3]);
        }
    }
}

// ---------------- GEMM2 via mma.sync bf16 (3-term split) --------------------
#define S2_A_HI 0
#define S2_A_LO 10240
#define S2_B_HI 20480
#define S2_B_LO 25600
#define STG2    30720
#define G2_TOTAL (2 * STG2)   // 61440

__global__ void __launch_bounds__(256)
gemm2_mma_kernel(__half* __restrict__ outh) {
    extern __shared__ char smem[];
    const uint32_t sm0 = smem_u32(smem);
    const int tid = threadIdx.x;
    const int wid = tid >> 5, lane = tid & 31;
    const int warp_m = wid & 3, warp_n = wid >> 2;
    const int rowBase = blockIdx.x * 128;

    float acc[2][4][4];
    #pragma unroll
    for (int i = 0; i < 2; i++)
        #pragma unroll
        for (int j = 0; j < 4; j++)
            #pragma unroll
            for (int t = 0; t < 4; t++) acc[i][j][t] = 0.f;

    auto load_stage = [&](int s, int kc) {
        int k0 = kc * 32;
        uint32_t sb = sm0 + s * STG2;
        #pragma unroll
        for (int i = 0; i < 2; i++) {
            int c = tid + 256 * i;
            int row = c >> 2, q = c & 3;
            int rg = rowBase + row; if (rg >= NN) rg = NN - 1;
            uint32_t o = row * ROWB + q * 16;
            cpa16(sb + S2_A_HI + o, g_h_hi + (size_t)rg * HID + k0 + q * 8);
            cpa16(sb + S2_A_LO + o, g_h_lo + (size_t)rg * HID + k0 + q * 8);
        }
        {
            int row = tid >> 2, q = tid & 3;
            uint32_t o = row * ROWB + q * 16;
            cpa16(sb + S2_B_HI + o, g_w2t_hi + (size_t)row * HID + k0 + q * 8);
            cpa16(sb + S2_B_LO + o, g_w2t_lo + (size_t)row * HID + k0 + q * 8);
        }
    };

    const int lq = lane >> 3, lr = lane & 7;

    auto compute_stage = [&](int s) {
        uint32_t sb = sm0 + s * STG2;
        #pragma unroll
        for (int ks = 0; ks < 2; ks++) {
            uint32_t ahi[2][4], alo[2][4];
            #pragma unroll
            for (int mb = 0; mb < 2; mb++) {
                int row = warp_m * 32 + mb * 16 + (lq & 1) * 8 + lr;
                int kb  = ks * 32 + (lq >> 1) * 16;
                uint32_t o = row * ROWB + kb;
                ldsm_x4(ahi[mb][0], ahi[mb][1], ahi[mb][2], ahi[mb][3], sb + S2_A_HI + o);
                ldsm_x4(alo[mb][0], alo[mb][1], alo[mb][2], alo[mb][3], sb + S2_A_LO + o);
            }
            #pragma unroll
            for (int g = 0; g < 2; g++) {
                int row = warp_n * 32 + g * 16 + (lq >> 1) * 8 + lr;
                int kb  = ks * 32 + (lq & 1) * 16;
                uint32_t o = row * ROWB + kb;
                uint32_t bh0, bh1, bh2, bh3, bl0, bl1, bl2, bl3;
                ldsm_x4(bh0, bh1, bh2, bh3, sb + S2_B_HI + o);
                ldsm_x4(bl0, bl1, bl2, bl3, sb + S2_B_LO + o);
                #pragma unroll
                for (int mb = 0; mb < 2; mb++) {
                    mma_bf16_2(acc[mb][2*g],   ahi[mb], bh0, bh1);
                    mma_bf16_2(acc[mb][2*g],   ahi[mb], bl0, bl1);
                    mma_bf16_2(acc[mb][2*g],   alo[mb], bh0, bh1);
                    mma_bf16_2(acc[mb][2*g+1], ahi[mb], bh2, bh3);
                    mma_bf16_2(acc[mb][2*g+1], ahi[mb], bl2, bl3);
                    mma_bf16_2(acc[mb][2*g+1], alo[mb], bh2, bh3);
                }
            }
        }
    };

    load_stage(0, 0);
    CP_COMMIT();
    for (int kc = 0; kc < 8; kc++) {
        if (kc < 7) {
            load_stage((kc + 1) & 1, kc + 1);
            CP_COMMIT();
            CP_WAIT_1();
        } else {
            CP_WAIT_0();
        }
        __syncthreads();
        compute_stage(kc & 1);
        __syncthreads();
    }

    const int gid = lane >> 2, tg = lane & 3;
    #pragma unroll
    for (int mb = 0; mb < 2; mb++) {
        int r0 = rowBase + warp_m * 32 + mb * 16 + gid;
        int r1 = r0 + 8;
        #pragma unroll
        for (int nb = 0; nb < 4; nb++) {
            int col = warp_n * 32 + nb * 8 + tg * 2;
            if (r0 < NN)
                *(__half2*)&outh[(size_t)r0 * OUT_F + col] =
                    __floats2half2_rn(acc[mb][nb][0], acc[mb][nb][1]);
            if (r1 < NN)
                *(__half2*)&outh[(size_t)r1 * OUT_F + col] =
                    __floats2half2_rn(acc[mb][nb][2], acc[mb][nb][3]);
        }
    }
}

// ---------------- SpMM1 (+ ReLU + dropout + bf16 split) : warp per row ------
__global__ void __launch_bounds__(256)
spmm1_kernel(const void* __restrict__ a_col,
             const float* __restrict__ a_val,
             const int* __restrict__ drop_mask) {
    int warp = (blockIdx.x * blockDim.x + threadIdx.x) >> 5;
    int lane = threadIdx.x & 31;
    if (warp >= NN) return;
    const int is64 = g_is64;
    int e0 = g_rowptr[warp];
    int e1 = g_rowptr[warp + 1];

    float acc[8];
    #pragma unroll
    for (int j = 0; j < 8; j++) acc[j] = 0.f;

    int e = e0;
    for (; e + 7 < e1; e += 8) {
        int cc[8]; float vv[8]; uint4 q[8];
        #pragma unroll
        for (int j = 0; j < 8; j++) {
            cc[j] = load_idx(a_col, e + j, is64);
            vv[j] = __ldg(&a_val[e + j]);
        }
        #pragma unroll
        for (int j = 0; j < 8; j++)
            q[j] = __ldg((const uint4*)(g_xw1h + (size_t)cc[j] * HID) + lane);
        #pragma unroll
        for (int j = 0; j < 8; j++) {
            float2 f0 = __half22float2(*reinterpret_cast<__half2*>(&q[j].x));
            float2 f1 = __half22float2(*reinterpret_cast<__half2*>(&q[j].y));
            float2 f2 = __half22float2(*reinterpret_cast<__half2*>(&q[j].z));
            float2 f3 = __half22float2(*reinterpret_cast<__half2*>(&q[j].w));
            acc[0] = fmaf(vv[j], f0.x, acc[0]); acc[1] = fmaf(vv[j], f0.y, acc[1]);
            acc[2] = fmaf(vv[j], f1.x, acc[2]); acc[3] = fmaf(vv[j], f1.y, acc[3]);
            acc[4] = fmaf(vv[j], f2.x, acc[4]); acc[5] = fmaf(vv[j], f2.y, acc[5]);
            acc[6] = fmaf(vv[j], f3.x, acc[6]); acc[7] = fmaf(vv[j], f3.y, acc[7]);
        }
    }
    for (; e + 3 < e1; e += 4) {
        int cc[4]; float vv[4]; uint4 q[4];
        #pragma unroll
        for (int j = 0; j < 4; j++) {
            cc[j] = load_idx(a_col, e + j, is64);
            vv[j] = __ldg(&a_val[e + j]);
        }
        #pragma unroll
        for (int j = 0; j < 4; j++)
            q[j] = __ldg((const uint4*)(g_xw1h + (size_t)cc[j] * HID) + lane);
        #pragma unroll
        for (int j = 0; j < 4; j++) {
            float2 f0 = __half22float2(*reinterpret_cast<__half2*>(&q[j].x));
            float2 f1 = __half22float2(*reinterpret_cast<__half2*>(&q[j].y));
            float2 f2 = __half22float2(*reinterpret_cast<__half2*>(&q[j].z));
            float2 f3 = __half22float2(*reinterpret_cast<__half2*>(&q[j].w));
            acc[0] = fmaf(vv[j], f0.x, acc[0]); acc[1] = fmaf(vv[j], f0.y, acc[1]);
            acc[2] = fmaf(vv[j], f1.x, acc[2]); acc[3] = fmaf(vv[j], f1.y, acc[3]);
            acc[4] = fmaf(vv[j], f2.x, acc[4]); acc[5] = fmaf(vv[j], f2.y, acc[5]);
            acc[6] = fmaf(vv[j], f3.x, acc[6]); acc[7] = fmaf(vv[j], f3.y, acc[7]);
        }
    }
    for (; e < e1; e++) {
        int   col = load_idx(a_col, e, is64);
        float v   = __ldg(&a_val[e]);
        uint4 q = __ldg((const uint4*)(g_xw1h + (size_t)col * HID) + lane);
        float2 f0 = __half22float2(*reinterpret_cast<__half2*>(&q.x));
        float2 f1 = __half22float2(*reinterpret_cast<__half2*>(&q.y));
        float2 f2 = __half22float2(*reinterpret_cast<__half2*>(&q.z));
        float2 f3 = __half22float2(*reinterpret_cast<__half2*>(&q.w));
        acc[0] = fmaf(v, f0.x, acc[0]); acc[1] = fmaf(v, f0.y, acc[1]);
        acc[2] = fmaf(v, f1.x, acc[2]); acc[3] = fmaf(v, f1.y, acc[3]);
        acc[4] = fmaf(v, f2.x, acc[4]); acc[5] = fmaf(v, f2.y, acc[5]);
        acc[6] = fmaf(v, f3.x, acc[6]); acc[7] = fmaf(v, f3.y, acc[7]);
    }

    const int4* mrow = (const int4*)(drop_mask + (size_t)warp * HID) + lane * 2;
    int4 m0 = __ldg(mrow);
    int4 m1 = __ldg(mrow + 1);

    float r[8];
    r[0] = fmaxf(acc[0], 0.f) * (float)m0.x * 2.0f;
    r[1] = fmaxf(acc[1], 0.f) * (float)m0.y * 2.0f;
    r[2] = fmaxf(acc[2], 0.f) * (float)m0.z * 2.0f;
    r[3] = fmaxf(acc[3], 0.f) * (float)m0.w * 2.0f;
    r[4] = fmaxf(acc[4], 0.f) * (float)m1.x * 2.0f;
    r[5] = fmaxf(acc[5], 0.f) * (float)m1.y * 2.0f;
    r[6] = fmaxf(acc[6], 0.f) * (float)m1.z * 2.0f;
    r[7] = fmaxf(acc[7], 0.f) * (float)m1.w * 2.0f;

    uint4 hi, lo;
    float h0, h1;
    h0 = bf_round(r[0]); h1 = bf_round(r[1]);
    hi.x = bf2_pack(r[0], r[1]); lo.x = bf2_pack(r[0] - h0, r[1] - h1);
    h0 = bf_round(r[2]); h1 = bf_round(r[3]);
    hi.y = bf2_pack(r[2], r[3]); lo.y = bf2_pack(r[2] - h0, r[3] - h1);
    h0 = bf_round(r[4]); h1 = bf_round(r[5]);
    hi.z = bf2_pack(r[4], r[5]); lo.z = bf2_pack(r[4] - h0, r[5] - h1);
    h0 = bf_round(r[6]); h1 = bf_round(r[7]);
    hi.w = bf2_pack(r[6], r[7]); lo.w = bf2_pack(r[6] - h0, r[7] - h1);

    *(uint4*)(g_h_hi + (size_t)warp * HID + lane * 8) = hi;
    *(uint4*)(g_h_lo + (size_t)warp * HID + lane * 8) = lo;
}

// ---------------- SpMM2 + log_softmax : warp per row (fp16 gather) ----------
__global__ void __launch_bounds__(256)
spmm2_lsm_kernel(const void* __restrict__ a_col,
                 const float* __restrict__ a_val,
                 float* __restrict__ out) {
    int warp = (blockIdx.x * blockDim.x + threadIdx.x) >> 5;
    int lane = threadIdx.x & 31;
    if (warp >= NN) return;
    const int is64 = g_is64;
    int e0 = g_rowptr[warp];
    int e1 = g_rowptr[warp + 1];

    float a0 = 0.f, a1 = 0.f;
    int e = e0;
    for (; e + 7 < e1; e += 8) {
        int cc[8]; float vv[8]; uint32_t u[8];
        #pragma unroll
        for (int j = 0; j < 8; j++) {
            cc[j] = load_idx(a_col, e + j, is64);
            vv[j] = __ldg(&a_val[e + j]);
        }
        #pragma unroll
        for (int j = 0; j < 8; j++)
            u[j] = __ldg((const uint32_t*)(g_hw2h + (size_t)cc[j] * OUT_F) + lane);
        #pragma unroll
        for (int j = 0; j < 8; j++) {
            float2 f = __half22float2(*reinterpret_cast<__half2*>(&u[j]));
            a0 = fmaf(vv[j], f.x, a0);
            a1 = fmaf(vv[j], f.y, a1);
        }
    }
    for (; e < e1; e++) {
        int   col = load_idx(a_col, e, is64);
        float v   = __ldg(&a_val[e]);
        uint32_t u = __ldg((const uint32_t*)(g_hw2h + (size_t)col * OUT_F) + lane);
        float2 f = __half22float2(*reinterpret_cast<__half2*>(&u));
        a0 = fmaf(v, f.x, a0);
        a1 = fmaf(v, f.y, a1);
    }

    float m = fmaxf(a0, a1);
    #pragma unroll
    for (int off = 16; off > 0; off >>= 1)
        m = fmaxf(m, __shfl_xor_sync(0xFFFFFFFFu, m, off));
    float s = expf(a0 - m) + expf(a1 - m);
    #pragma unroll
    for (int off = 16; off > 0; off >>= 1)
        s += __shfl_xor_sync(0xFFFFFFFFu, s, off);
    float ls = logf(s) + m;

    out[(size_t)warp * OUT_F + lane * 2]     = a0 - ls;
    out[(size_t)warp * OUT_F + lane * 2 + 1] = a1 - ls;
}

// ---------------- launch ----------------------------------------------------
extern "C" void kernel_launch(void* const* d_in, const int* in_sizes, int n_in,
                              void* d_out, int out_size) {
    const float* X     = (const float*)d_in[0];
    const float* W1    = (const float*)d_in[1];
    const float* W2    = (const float*)d_in[2];
    const void*  a_row = d_in[3];
    const void*  a_col = d_in[4];
    const float* a_val = (const float*)d_in[5];
    const int*   dmask = (const int*)d_in[6];
    float*       out   = (float*)d_out;

    const int E = in_sizes[5];

    __half *p_xw1h, *p_hw2h;
    cudaGetSymbolAddress((void**)&p_xw1h, g_xw1h);
    cudaGetSymbolAddress((void**)&p_hw2h, g_hw2h);

    static int smem_set = 0;
    if (!smem_set) {
        cudaFuncSetAttribute(gemm1_mma_kernel,
                             cudaFuncAttributeMaxDynamicSharedMemorySize, G1_TOTAL);
        cudaFuncSetAttribute(gemm2_mma_kernel,
                             cudaFuncAttributeMaxDynamicSharedMemorySize, G2_TOTAL);
        smem_set = 1;
    }

    // idx0: detect index dtype
    detect_idx_kernel<<<1, 32>>>(a_col, E);

    // idx1: merged weight preps
    prep_w_kernel<<<(IN_F * HID + HID * OUT_F + 255) / 256, 256>>>(W1, W2);

    // idx2: row pointers
    build_rowptr_kernel<<<(NN + 1 + 255) / 256, 256>>>(a_row, E);

    // idx3 (profiled slot): GEMM1 xw1 = X @ W1 -> fp16
    {
        dim3 grid(HID / 128, (NN + 127) / 128);   // x-major: N-pair shares X via L2
        gemm1_mma_kernel<<<grid, 256, G1_TOTAL>>>(X, p_xw1h);
    }

    // idx4: SpMM1 + relu + dropout -> h (bf16 hi/lo)
    spmm1_kernel<<<(NN * 32 + 255) / 256, 256>>>(a_col, a_val, dmask);

    // idx5: GEMM2 hw2 = h @ W2 -> fp16
    gemm2_mma_kernel<<<(NN + 127) / 128, 256, G2_TOTAL>>>(p_hw2h);

    // idx6: SpMM2 + log_softmax -> out
    spmm2_lsm_kernel<<<(NN * 32 + 255) / 256, 256>>>(a_col, a_val, out);
}

// round 13
// speedup vs baseline: 1.0863x; 1.0863x over previous
#include <cuda_runtime.h>
#include <cuda_bf16.h>
#include <cuda_fp16.h>
#include <math.h>
#include <stdint.h>

// Problem constants
#define NN    50000
#define EE    800000
#define IN_F  512
#define HID   256
#define OUT_F 64

// ---------------- scratch (static device globals; no allocs) ----------------
__device__ __half g_xw1h[(size_t)NN * HID];   // X @ W1 (fp16 gather table)
__device__ __half g_hw2h[(size_t)NN * OUT_F]; // h @ W2 (fp16 gather table)
__device__ int   g_rowptr[NN + 1];
__device__ int   g_is64;
__device__ __nv_bfloat16 g_w1t_hi[(size_t)HID * IN_F]; // W1^T bf16 hi [256,512]
__device__ __nv_bfloat16 g_w1t_lo[(size_t)HID * IN_F]; // W1^T bf16 lo
__device__ __nv_bfloat16 g_h_hi[(size_t)NN * HID];     // h split hi [50000,256]
__device__ __nv_bfloat16 g_h_lo[(size_t)NN * HID];     // h split lo
__device__ __nv_bfloat16 g_w2t_hi[(size_t)OUT_F * HID]; // W2^T bf16 hi [64,256]
__device__ __nv_bfloat16 g_w2t_lo[(size_t)OUT_F * HID]; // W2^T bf16 lo

// ======================= PTX helpers ========================================
__device__ __forceinline__ uint32_t smem_u32(const void* p) {
    uint32_t a;
    asm("{ .reg .u64 t; cvta.to.shared.u64 t, %1; cvt.u32.u64 %0, t; }"
        : "=r"(a) : "l"(p));
    return a;
}
__device__ __forceinline__ void cpa16(uint32_t dst, const void* src) {
    asm volatile("cp.async.cg.shared.global [%0], [%1], 16;"
                 :: "r"(dst), "l"(src) : "memory");
}
#define CP_COMMIT()  asm volatile("cp.async.commit_group;" ::: "memory")
#define CP_WAIT_1()  asm volatile("cp.async.wait_group 1;" ::: "memory")
#define CP_WAIT_0()  asm volatile("cp.async.wait_group 0;" ::: "memory")

__device__ __forceinline__ void ldsm_x4(uint32_t& r0, uint32_t& r1,
                                        uint32_t& r2, uint32_t& r3, uint32_t addr) {
    asm volatile("ldmatrix.sync.aligned.m8n8.x4.shared.b16 {%0,%1,%2,%3}, [%4];"
                 : "=r"(r0), "=r"(r1), "=r"(r2), "=r"(r3) : "r"(addr));
}
__device__ __forceinline__ void mma_bf16_2(float* c, const uint32_t* a,
                                           uint32_t b0, uint32_t b1) {
    asm volatile(
        "mma.sync.aligned.m16n8k16.row.col.f32.bf16.bf16.f32 "
        "{%0,%1,%2,%3}, {%4,%5,%6,%7}, {%8,%9}, {%0,%1,%2,%3};"
        : "+f"(c[0]), "+f"(c[1]), "+f"(c[2]), "+f"(c[3])
        : "r"(a[0]), "r"(a[1]), "r"(a[2]), "r"(a[3]), "r"(b0), "r"(b1));
}
__device__ __forceinline__ uint32_t bf2_pack(float a, float b) {
    __nv_bfloat162 t = __floats2bfloat162_rn(a, b);
    return *reinterpret_cast<uint32_t*>(&t);
}
__device__ __forceinline__ float bf_round(float x) {
    return __bfloat162float(__float2bfloat16_rn(x));
}
__device__ __forceinline__ uint32_t h2_pack(float a, float b) {
    __half2 t = __floats2half2_rn(a, b);
    return *reinterpret_cast<uint32_t*>(&t);
}

__device__ __forceinline__ int load_idx(const void* p, int i, int is64) {
    if (is64) return (int)((const long long*)p)[i];
    return ((const int*)p)[i];
}

// ---------------- merged prep: weight splits + rowptr (+ idx detection) -----
// blocks [0, WPREP_BLKS): W1/W2 bf16 hi/lo split
// blocks [WPREP_BLKS, ...): rowptr via binary search; each thread detects
//   int32-vs-int64 itself (32 cached probes), block WPREP_BLKS publishes g_is64.
#define WPREP_ITEMS (IN_F * HID + HID * OUT_F)     // 147456
#define WPREP_BLKS  ((WPREP_ITEMS + 255) / 256)    // 576
#define RPTR_BLKS   ((NN + 1 + 255) / 256)         // 196

__device__ __forceinline__ int detect_is64(const void* a_col_raw, int E) {
    const long long* p = (const long long*)a_col_raw;
    int ok = 1;
    #pragma unroll 4
    for (int i = 0; i < 16; i++) {
        long long v = p[i];
        if (v < 0 || v >= NN) { ok = 0; break; }
    }
    if (ok) {
        #pragma unroll 4
        for (int i = 0; i < 16; i++) {
            long long v = p[E / 2 + i];
            if (v < 0 || v >= NN) { ok = 0; break; }
        }
    }
    return ok;
}

__global__ void prep_all_kernel(const float* __restrict__ W1,
                                const float* __restrict__ W2,
                                const void* __restrict__ a_row,
                                const void* __restrict__ a_col,
                                int E) {
    int b = blockIdx.x;
    if (b < WPREP_BLKS) {
        int idx = b * 256 + threadIdx.x;
        if (idx < IN_F * HID) {
            int n = idx >> 9, k = idx & 511;
            float v = W1[(size_t)k * HID + n];
            __nv_bfloat16 h = __float2bfloat16_rn(v);
            g_w1t_hi[idx] = h;
            g_w1t_lo[idx] = __float2bfloat16_rn(v - __bfloat162float(h));
        } else {
            int j = idx - IN_F * HID;
            if (j < HID * OUT_F) {
                int n = j >> 8, k = j & 255;
                float v = W2[(size_t)k * OUT_F + n];
                __nv_bfloat16 h = __float2bfloat16_rn(v);
                g_w2t_hi[j] = h;
                g_w2t_lo[j] = __float2bfloat16_rn(v - __bfloat162float(h));
            }
        }
    } else {
        // rowptr blocks: per-thread dtype detection (probes of a_col)
        int is64 = detect_is64(a_col, E);
        int r = (b - WPREP_BLKS) * 256 + threadIdx.x;
        if (b == WPREP_BLKS && threadIdx.x == 0) g_is64 = is64;  // for spmm kernels
        if (r > NN) return;
        if (r == NN) { g_rowptr[NN] = E; return; }
        int lo = 0, hi = E;
        while (lo < hi) {
            int mid = (lo + hi) >> 1;
            if (load_idx(a_row, mid, is64) < r) lo = mid + 1; else hi = mid;
        }
        g_rowptr[r] = lo;
    }
}

// ---------------- GEMM1: X@W1 CTA 128x128, bf16 3-term, reg-staged X --------
// (R11 proven config: 80KB smem -> 2 CTAs/SM, 256 thr, 2 syncs/k-chunk)
#define ROWB   80
#define G1_AHI 0          // 2 x 10240
#define G1_ALO 20480
#define G1_BHI 40960
#define G1_BLO 61440
#define G1_TOTAL 81920

__global__ void __launch_bounds__(256, 2)
gemm1_mma_kernel(const float* __restrict__ X, __half* __restrict__ outh) {
    extern __shared__ char smem[];
    const uint32_t sm0 = smem_u32(smem);
    const int tid = threadIdx.x;
    const int wid = tid >> 5, lane = tid & 31;
    const int warp_m = wid & 3, warp_n = wid >> 2;
    const int colBase = blockIdx.x * 128;   // 0 or 128 (HID)
    const int rowBase = blockIdx.y * 128;

    float acc[2][8][4];
    #pragma unroll
    for (int i = 0; i < 2; i++)
        #pragma unroll
        for (int j = 0; j < 8; j++)
            #pragma unroll
            for (int t = 0; t < 4; t++) acc[i][j][t] = 0.f;

    const int xrow = tid >> 3;   // 0..31 (+32i)
    const int xq   = tid & 7;    // 16B chunk in 128B row
    float4 xr[4];

    auto ldg_x = [&](int kc) {
        int k0 = kc * 32;
        #pragma unroll
        for (int i = 0; i < 4; i++) {
            int rg = rowBase + xrow + 32 * i;
            if (rg >= NN) rg = NN - 1;
            xr[i] = __ldg((const float4*)(X + (size_t)rg * IN_F + k0 + xq * 4));
        }
    };
    auto convert_x = [&](int s) {
        char* ah = smem + G1_AHI + s * 10240;
        char* al = smem + G1_ALO + s * 10240;
        #pragma unroll
        for (int i = 0; i < 4; i++) {
            int row = xrow + 32 * i;
            float4 v = xr[i];
            float h0 = bf_round(v.x), h1 = bf_round(v.y);
            float h2 = bf_round(v.z), h3 = bf_round(v.w);
            uint2 hi = make_uint2(bf2_pack(v.x, v.y), bf2_pack(v.z, v.w));
            uint2 lo = make_uint2(bf2_pack(v.x - h0, v.y - h1),
                                  bf2_pack(v.z - h2, v.w - h3));
            *(uint2*)(ah + row * ROWB + xq * 8) = hi;
            *(uint2*)(al + row * ROWB + xq * 8) = lo;
        }
    };
    auto load_b = [&](int s, int kc) {
        int k0 = kc * 32;
        uint32_t bh = sm0 + G1_BHI + s * 10240;
        uint32_t bl = sm0 + G1_BLO + s * 10240;
        #pragma unroll
        for (int i = 0; i < 2; i++) {
            int c = tid + 256 * i;          // 0..511 : 128 B-rows x 4 chunks
            int row = c >> 2, q = c & 3;
            uint32_t o = row * ROWB + q * 16;
            cpa16(bh + o, g_w1t_hi + (size_t)(colBase + row) * IN_F + k0 + q * 8);
            cpa16(bl + o, g_w1t_lo + (size_t)(colBase + row) * IN_F + k0 + q * 8);
        }
    };

    const int lq = lane >> 3, lr = lane & 7;

    auto compute_stage = [&](int s) {
        uint32_t ah = sm0 + G1_AHI + s * 10240;
        uint32_t al = sm0 + G1_ALO + s * 10240;
        uint32_t bhb = sm0 + G1_BHI + s * 10240;
        uint32_t blb = sm0 + G1_BLO + s * 10240;
        #pragma unroll
        for (int ks = 0; ks < 2; ks++) {
            uint32_t ahi[2][4], alo[2][4];
            #pragma unroll
            for (int mb = 0; mb < 2; mb++) {
                int row = warp_m * 32 + mb * 16 + (lq & 1) * 8 + lr;
                int kb  = ks * 32 + (lq >> 1) * 16;
                ldsm_x4(ahi[mb][0], ahi[mb][1], ahi[mb][2], ahi[mb][3],
                        ah + row * ROWB + kb);
                ldsm_x4(alo[mb][0], alo[mb][1], alo[mb][2], alo[mb][3],
                        al + row * ROWB + kb);
            }
            #pragma unroll
            for (int g = 0; g < 4; g++) {
                int row = warp_n * 64 + g * 16 + (lq >> 1) * 8 + lr;
                int kb  = ks * 32 + (lq & 1) * 16;
                uint32_t o = row * ROWB + kb;
                uint32_t bh0, bh1, bh2, bh3, bl0, bl1, bl2, bl3;
                ldsm_x4(bh0, bh1, bh2, bh3, bhb + o);
                ldsm_x4(bl0, bl1, bl2, bl3, blb + o);
                #pragma unroll
                for (int mb = 0; mb < 2; mb++) {
                    mma_bf16_2(acc[mb][2*g],   ahi[mb], bh0, bh1);
                    mma_bf16_2(acc[mb][2*g],   ahi[mb], bl0, bl1);
                    mma_bf16_2(acc[mb][2*g],   alo[mb], bh0, bh1);
                    mma_bf16_2(acc[mb][2*g+1], ahi[mb], bh2, bh3);
                    mma_bf16_2(acc[mb][2*g+1], ahi[mb], bl2, bl3);
                    mma_bf16_2(acc[mb][2*g+1], alo[mb], bh2, bh3);
                }
            }
        }
    };

    load_b(0, 0); CP_COMMIT();
    ldg_x(0);
    for (int kc = 0; kc < 16; kc++) {
        if (kc < 15) { load_b((kc + 1) & 1, kc + 1); CP_COMMIT(); }
        convert_x(kc & 1);              // own regs -> smem (self-consistent)
        if (kc < 15) ldg_x(kc + 1);     // prefetch next X chunk into regs
        if (kc < 15) CP_WAIT_1(); else CP_WAIT_0();
        __syncthreads();                // publish A converts + B(kc)
        compute_stage(kc & 1);
        __syncthreads();                // protect B/A buffers from next writes
    }

    const int gid = lane >> 2, tg = lane & 3;
    #pragma unroll
    for (int mb = 0; mb < 2; mb++) {
        int r0 = rowBase + warp_m * 32 + mb * 16 + gid;
        int r1 = r0 + 8;
        #pragma unroll
        for (int nb = 0; nb < 8; nb++) {
            int col = colBase + warp_n * 64 + nb * 8 + tg * 2;
            if (r0 < NN)
                *(__half2*)&outh[(size_t)r0 * HID + col] =
                    __floats2half2_rn(acc[mb][nb][0], acc[mb][nb][1]);
            if (r1 < NN)
                *(__half2*)&outh[(size_t)r1 * HID + col] =
                    __floats2half2_rn(acc[mb][nb][2], acc[mb][nb][3]);
        }
    }
}

// ---------------- GEMM2 via mma.sync bf16 (3-term split) --------------------
#define S2_A_HI 0
#define S2_A_LO 10240
#define S2_B_HI 20480
#define S2_B_LO 25600
#define STG2    30720
#define G2_TOTAL (2 * STG2)   // 61440

__global__ void __launch_bounds__(256)
gemm2_mma_kernel(__half* __restrict__ outh) {
    extern __shared__ char smem[];
    const uint32_t sm0 = smem_u32(smem);
    const int tid = threadIdx.x;
    const int wid = tid >> 5, lane = tid & 31;
    const int warp_m = wid & 3, warp_n = wid >> 2;
    const int rowBase = blockIdx.x * 128;

    float acc[2][4][4];
    #pragma unroll
    for (int i = 0; i < 2; i++)
        #pragma unroll
        for (int j = 0; j < 4; j++)
            #pragma unroll
            for (int t = 0; t < 4; t++) acc[i][j][t] = 0.f;

    auto load_stage = [&](int s, int kc) {
        int k0 = kc * 32;
        uint32_t sb = sm0 + s * STG2;
        #pragma unroll
        for (int i = 0; i < 2; i++) {
            int c = tid + 256 * i;
            int row = c >> 2, q = c & 3;
            int rg = rowBase + row; if (rg >= NN) rg = NN - 1;
            uint32_t o = row * ROWB + q * 16;
            cpa16(sb + S2_A_HI + o, g_h_hi + (size_t)rg * HID + k0 + q * 8);
            cpa16(sb + S2_A_LO + o, g_h_lo + (size_t)rg * HID + k0 + q * 8);
        }
        {
            int row = tid >> 2, q = tid & 3;
            uint32_t o = row * ROWB + q * 16;
            cpa16(sb + S2_B_HI + o, g_w2t_hi + (size_t)row * HID + k0 + q * 8);
            cpa16(sb + S2_B_LO + o, g_w2t_lo + (size_t)row * HID + k0 + q * 8);
        }
    };

    const int lq = lane >> 3, lr = lane & 7;

    auto compute_stage = [&](int s) {
        uint32_t sb = sm0 + s * STG2;
        #pragma unroll
        for (int ks = 0; ks < 2; ks++) {
            uint32_t ahi[2][4], alo[2][4];
            #pragma unroll
            for (int mb = 0; mb < 2; mb++) {
                int row = warp_m * 32 + mb * 16 + (lq & 1) * 8 + lr;
                int kb  = ks * 32 + (lq >> 1) * 16;
                uint32_t o = row * ROWB + kb;
                ldsm_x4(ahi[mb][0], ahi[mb][1], ahi[mb][2], ahi[mb][3], sb + S2_A_HI + o);
                ldsm_x4(alo[mb][0], alo[mb][1], alo[mb][2], alo[mb][3], sb + S2_A_LO + o);
            }
            #pragma unroll
            for (int g = 0; g < 2; g++) {
                int row = warp_n * 32 + g * 16 + (lq >> 1) * 8 + lr;
                int kb  = ks * 32 + (lq & 1) * 16;
                uint32_t o = row * ROWB + kb;
                uint32_t bh0, bh1, bh2, bh3, bl0, bl1, bl2, bl3;
                ldsm_x4(bh0, bh1, bh2, bh3, sb + S2_B_HI + o);
                ldsm_x4(bl0, bl1, bl2, bl3, sb + S2_B_LO + o);
                #pragma unroll
                for (int mb = 0; mb < 2; mb++) {
                    mma_bf16_2(acc[mb][2*g],   ahi[mb], bh0, bh1);
                    mma_bf16_2(acc[mb][2*g],   ahi[mb], bl0, bl1);
                    mma_bf16_2(acc[mb][2*g],   alo[mb], bh0, bh1);
                    mma_bf16_2(acc[mb][2*g+1], ahi[mb], bh2, bh3);
                    mma_bf16_2(acc[mb][2*g+1], ahi[mb], bl2, bl3);
                    mma_bf16_2(acc[mb][2*g+1], alo[mb], bh2, bh3);
                }
            }
        }
    };

    load_stage(0, 0);
    CP_COMMIT();
    for (int kc = 0; kc < 8; kc++) {
        if (kc < 7) {
            load_stage((kc + 1) & 1, kc + 1);
            CP_COMMIT();
            CP_WAIT_1();
        } else {
            CP_WAIT_0();
        }
        __syncthreads();
        compute_stage(kc & 1);
        __syncthreads();
    }

    const int gid = lane >> 2, tg = lane & 3;
    #pragma unroll
    for (int mb = 0; mb < 2; mb++) {
        int r0 = rowBase + warp_m * 32 + mb * 16 + gid;
        int r1 = r0 + 8;
        #pragma unroll
        for (int nb = 0; nb < 4; nb++) {
            int col = warp_n * 32 + nb * 8 + tg * 2;
            if (r0 < NN)
                *(__half2*)&outh[(size_t)r0 * OUT_F + col] =
                    __floats2half2_rn(acc[mb][nb][0], acc[mb][nb][1]);
            if (r1 < NN)
                *(__half2*)&outh[(size_t)r1 * OUT_F + col] =
                    __floats2half2_rn(acc[mb][nb][2], acc[mb][nb][3]);
        }
    }
}

// ---------------- SpMM1 (+ ReLU + dropout + bf16 split) : warp per row ------
__global__ void __launch_bounds__(256)
spmm1_kernel(const void* __restrict__ a_col,
             const float* __restrict__ a_val,
             const int* __restrict__ drop_mask) {
    int warp = (blockIdx.x * blockDim.x + threadIdx.x) >> 5;
    int lane = threadIdx.x & 31;
    if (warp >= NN) return;
    const int is64 = g_is64;
    int e0 = g_rowptr[warp];
    int e1 = g_rowptr[warp + 1];

    float acc[8];
    #pragma unroll
    for (int j = 0; j < 8; j++) acc[j] = 0.f;

    int e = e0;
    for (; e + 7 < e1; e += 8) {
        int cc[8]; float vv[8]; uint4 q[8];
        #pragma unroll
        for (int j = 0; j < 8; j++) {
            cc[j] = load_idx(a_col, e + j, is64);
            vv[j] = __ldg(&a_val[e + j]);
        }
        #pragma unroll
        for (int j = 0; j < 8; j++)
            q[j] = __ldg((const uint4*)(g_xw1h + (size_t)cc[j] * HID) + lane);
        #pragma unroll
        for (int j = 0; j < 8; j++) {
            float2 f0 = __half22float2(*reinterpret_cast<__half2*>(&q[j].x));
            float2 f1 = __half22float2(*reinterpret_cast<__half2*>(&q[j].y));
            float2 f2 = __half22float2(*reinterpret_cast<__half2*>(&q[j].z));
            float2 f3 = __half22float2(*reinterpret_cast<__half2*>(&q[j].w));
            acc[0] = fmaf(vv[j], f0.x, acc[0]); acc[1] = fmaf(vv[j], f0.y, acc[1]);
            acc[2] = fmaf(vv[j], f1.x, acc[2]); acc[3] = fmaf(vv[j], f1.y, acc[3]);
            acc[4] = fmaf(vv[j], f2.x, acc[4]); acc[5] = fmaf(vv[j], f2.y, acc[5]);
            acc[6] = fmaf(vv[j], f3.x, acc[6]); acc[7] = fmaf(vv[j], f3.y, acc[7]);
        }
    }
    for (; e + 3 < e1; e += 4) {
        int cc[4]; float vv[4]; uint4 q[4];
        #pragma unroll
        for (int j = 0; j < 4; j++) {
            cc[j] = load_idx(a_col, e + j, is64);
            vv[j] = __ldg(&a_val[e + j]);
        }
        #pragma unroll
        for (int j = 0; j < 4; j++)
            q[j] = __ldg((const uint4*)(g_xw1h + (size_t)cc[j] * HID) + lane);
        #pragma unroll
        for (int j = 0; j < 4; j++) {
            float2 f0 = __half22float2(*reinterpret_cast<__half2*>(&q[j].x));
            float2 f1 = __half22float2(*reinterpret_cast<__half2*>(&q[j].y));
            float2 f2 = __half22float2(*reinterpret_cast<__half2*>(&q[j].z));
            float2 f3 = __half22float2(*reinterpret_cast<__half2*>(&q[j].w));
            acc[0] = fmaf(vv[j], f0.x, acc[0]); acc[1] = fmaf(vv[j], f0.y, acc[1]);
            acc[2] = fmaf(vv[j], f1.x, acc[2]); acc[3] = fmaf(vv[j], f1.y, acc[3]);
            acc[4] = fmaf(vv[j], f2.x, acc[4]); acc[5] = fmaf(vv[j], f2.y, acc[5]);
            acc[6] = fmaf(vv[j], f3.x, acc[6]); acc[7] = fmaf(vv[j], f3.y, acc[7]);
        }
    }
    for (; e < e1; e++) {
        int   col = load_idx(a_col, e, is64);
        float v   = __ldg(&a_val[e]);
        uint4 q = __ldg((const uint4*)(g_xw1h + (size_t)col * HID) + lane);
        float2 f0 = __half22float2(*reinterpret_cast<__half2*>(&q.x));
        float2 f1 = __half22float2(*reinterpret_cast<__half2*>(&q.y));
        float2 f2 = __half22float2(*reinterpret_cast<__half2*>(&q.z));
        float2 f3 = __half22float2(*reinterpret_cast<__half2*>(&q.w));
        acc[0] = fmaf(v, f0.x, acc[0]); acc[1] = fmaf(v, f0.y, acc[1]);
        acc[2] = fmaf(v, f1.x, acc[2]); acc[3] = fmaf(v, f1.y, acc[3]);
        acc[4] = fmaf(v, f2.x, acc[4]); acc[5] = fmaf(v, f2.y, acc[5]);
        acc[6] = fmaf(v, f3.x, acc[6]); acc[7] = fmaf(v, f3.y, acc[7]);
    }

    const int4* mrow = (const int4*)(drop_mask + (size_t)warp * HID) + lane * 2;
    int4 m0 = __ldg(mrow);
    int4 m1 = __ldg(mrow + 1);

    float r[8];
    r[0] = fmaxf(acc[0], 0.f) * (float)m0.x * 2.0f;
    r[1] = fmaxf(acc[1], 0.f) * (float)m0.y * 2.0f;
    r[2] = fmaxf(acc[2], 0.f) * (float)m0.z * 2.0f;
    r[3] = fmaxf(acc[3], 0.f) * (float)m0.w * 2.0f;
    r[4] = fmaxf(acc[4], 0.f) * (float)m1.x * 2.0f;
    r[5] = fmaxf(acc[5], 0.f) * (float)m1.y * 2.0f;
    r[6] = fmaxf(acc[6], 0.f) * (float)m1.z * 2.0f;
    r[7] = fmaxf(acc[7], 0.f) * (float)m1.w * 2.0f;

    uint4 hi, lo;
    float h0, h1;
    h0 = bf_round(r[0]); h1 = bf_round(r[1]);
    hi.x = bf2_pack(r[0], r[1]); lo.x = bf2_pack(r[0] - h0, r[1] - h1);
    h0 = bf_round(r[2]); h1 = bf_round(r[3]);
    hi.y = bf2_pack(r[2], r[3]); lo.y = bf2_pack(r[2] - h0, r[3] - h1);
    h0 = bf_round(r[4]); h1 = bf_round(r[5]);
    hi.z = bf2_pack(r[4], r[5]); lo.z = bf2_pack(r[4] - h0, r[5] - h1);
    h0 = bf_round(r[6]); h1 = bf_round(r[7]);
    hi.w = bf2_pack(r[6], r[7]); lo.w = bf2_pack(r[6] - h0, r[7] - h1);

    *(uint4*)(g_h_hi + (size_t)warp * HID + lane * 8) = hi;
    *(uint4*)(g_h_lo + (size_t)warp * HID + lane * 8) = lo;
}

// ---------------- SpMM2 + log_softmax : warp per row (fp16 gather) ----------
__global__ void __launch_bounds__(256)
spmm2_lsm_kernel(const void* __restrict__ a_col,
                 const float* __restrict__ a_val,
                 float* __restrict__ out) {
    int warp = (blockIdx.x * blockDim.x + threadIdx.x) >> 5;
    int lane = threadIdx.x & 31;
    if (warp >= NN) return;
    const int is64 = g_is64;
    int e0 = g_rowptr[warp];
    int e1 = g_rowptr[warp + 1];

    float a0 = 0.f, a1 = 0.f;
    int e = e0;
    for (; e + 7 < e1; e += 8) {
        int cc[8]; float vv[8]; uint32_t u[8];
        #pragma unroll
        for (int j = 0; j < 8; j++) {
            cc[j] = load_idx(a_col, e + j, is64);
            vv[j] = __ldg(&a_val[e + j]);
        }
        #pragma unroll
        for (int j = 0; j < 8; j++)
            u[j] = __ldg((const uint32_t*)(g_hw2h + (size_t)cc[j] * OUT_F) + lane);
        #pragma unroll
        for (int j = 0; j < 8; j++) {
            float2 f = __half22float2(*reinterpret_cast<__half2*>(&u[j]));
            a0 = fmaf(vv[j], f.x, a0);
            a1 = fmaf(vv[j], f.y, a1);
        }
    }
    for (; e < e1; e++) {
        int   col = load_idx(a_col, e, is64);
        float v   = __ldg(&a_val[e]);
        uint32_t u = __ldg((const uint32_t*)(g_hw2h + (size_t)col * OUT_F) + lane);
        float2 f = __half22float2(*reinterpret_cast<__half2*>(&u));
        a0 = fmaf(v, f.x, a0);
        a1 = fmaf(v, f.y, a1);
    }

    float m = fmaxf(a0, a1);
    #pragma unroll
    for (int off = 16; off > 0; off >>= 1)
        m = fmaxf(m, __shfl_xor_sync(0xFFFFFFFFu, m, off));
    float s = expf(a0 - m) + expf(a1 - m);
    #pragma unroll
    for (int off = 16; off > 0; off >>= 1)
        s += __shfl_xor_sync(0xFFFFFFFFu, s, off);
    float ls = logf(s) + m;

    out[(size_t)warp * OUT_F + lane * 2]     = a0 - ls;
    out[(size_t)warp * OUT_F + lane * 2 + 1] = a1 - ls;
}

// ---------------- launch ----------------------------------------------------
extern "C" void kernel_launch(void* const* d_in, const int* in_sizes, int n_in,
                              void* d_out, int out_size) {
    const float* X     = (const float*)d_in[0];
    const float* W1    = (const float*)d_in[1];
    const float* W2    = (const float*)d_in[2];
    const void*  a_row = d_in[3];
    const void*  a_col = d_in[4];
    const float* a_val = (const float*)d_in[5];
    const int*   dmask = (const int*)d_in[6];
    float*       out   = (float*)d_out;

    const int E = in_sizes[5];

    __half *p_xw1h, *p_hw2h;
    cudaGetSymbolAddress((void**)&p_xw1h, g_xw1h);
    cudaGetSymbolAddress((void**)&p_hw2h, g_hw2h);

    static int smem_set = 0;
    if (!smem_set) {
        cudaFuncSetAttribute(gemm1_mma_kernel,
                             cudaFuncAttributeMaxDynamicSharedMemorySize, G1_TOTAL);
        cudaFuncSetAttribute(gemm2_mma_kernel,
                             cudaFuncAttributeMaxDynamicSharedMemorySize, G2_TOTAL);
        smem_set = 1;
    }

    // idx0: merged prep (W splits + rowptr + idx-dtype detection)
    prep_all_kernel<<<WPREP_BLKS + RPTR_BLKS, 256>>>(W1, W2, a_row, a_col, E);

    // idx1: GEMM1 xw1 = X @ W1 -> fp16
    {
        dim3 grid(HID / 128, (NN + 127) / 128);   // x-major: N-pair shares X via L2
        gemm1_mma_kernel<<<grid, 256, G1_TOTAL>>>(X, p_xw1h);
    }

    // idx2: SpMM1 + relu + dropout -> h (bf16 hi/lo)
    spmm1_kernel<<<(NN * 32 + 255) / 256, 256>>>(a_col, a_val, dmask);

    // idx3: GEMM2 hw2 = h @ W2 -> fp16
    gemm2_mma_kernel<<<(NN + 127) / 128, 256, G2_TOTAL>>>(p_hw2h);

    // idx4: SpMM2 + log_softmax -> out
    spmm2_lsm_kernel<<<(NN * 32 + 255) / 256, 256>>>(a_col, a_val, out);
}

// round 14
// speedup vs baseline: 1.1063x; 1.0184x over previous
#include <cuda_runtime.h>
#include <cuda_bf16.h>
#include <cuda_fp16.h>
#include <math.h>
#include <stdint.h>

// Problem constants
#define NN    50000
#define EE    800000
#define IN_F  512
#define HID   256
#define OUT_F 64

// ---------------- scratch (static device globals; no allocs) ----------------
__device__ __half g_xw1h[(size_t)NN * HID];   // X @ W1 (fp16 gather table)
__device__ __half g_hw2h[(size_t)NN * OUT_F]; // h @ W2 (fp16 gather table)
__device__ int   g_rowptr[NN + 1];
__device__ int   g_is64;
__device__ __nv_bfloat16 g_w1t_hi[(size_t)HID * IN_F]; // W1^T bf16 hi [256,512]
__device__ __nv_bfloat16 g_w1t_lo[(size_t)HID * IN_F]; // W1^T bf16 lo
__device__ __nv_bfloat16 g_h_hi[(size_t)NN * HID];     // h split hi [50000,256]
__device__ __nv_bfloat16 g_h_lo[(size_t)NN * HID];     // h split lo
__device__ __nv_bfloat16 g_w2t_hi[(size_t)OUT_F * HID]; // W2^T bf16 hi [64,256]
__device__ __nv_bfloat16 g_w2t_lo[(size_t)OUT_F * HID]; // W2^T bf16 lo

// ======================= PTX helpers ========================================
__device__ __forceinline__ uint32_t smem_u32(const void* p) {
    uint32_t a;
    asm("{ .reg .u64 t; cvta.to.shared.u64 t, %1; cvt.u32.u64 %0, t; }"
        : "=r"(a) : "l"(p));
    return a;
}
__device__ __forceinline__ void cpa16(uint32_t dst, const void* src) {
    asm volatile("cp.async.cg.shared.global [%0], [%1], 16;"
                 :: "r"(dst), "l"(src) : "memory");
}
#define CP_COMMIT()  asm volatile("cp.async.commit_group;" ::: "memory")
#define CP_WAIT_1()  asm volatile("cp.async.wait_group 1;" ::: "memory")
#define CP_WAIT_0()  asm volatile("cp.async.wait_group 0;" ::: "memory")

__device__ __forceinline__ void ldsm_x4(uint32_t& r0, uint32_t& r1,
                                        uint32_t& r2, uint32_t& r3, uint32_t addr) {
    asm volatile("ldmatrix.sync.aligned.m8n8.x4.shared.b16 {%0,%1,%2,%3}, [%4];"
                 : "=r"(r0), "=r"(r1), "=r"(r2), "=r"(r3) : "r"(addr));
}
__device__ __forceinline__ void mma_bf16_2(float* c, const uint32_t* a,
                                           uint32_t b0, uint32_t b1) {
    asm volatile(
        "mma.sync.aligned.m16n8k16.row.col.f32.bf16.bf16.f32 "
        "{%0,%1,%2,%3}, {%4,%5,%6,%7}, {%8,%9}, {%0,%1,%2,%3};"
        : "+f"(c[0]), "+f"(c[1]), "+f"(c[2]), "+f"(c[3])
        : "r"(a[0]), "r"(a[1]), "r"(a[2]), "r"(a[3]), "r"(b0), "r"(b1));
}
__device__ __forceinline__ uint32_t bf2_pack(float a, float b) {
    __nv_bfloat162 t = __floats2bfloat162_rn(a, b);
    return *reinterpret_cast<uint32_t*>(&t);
}
__device__ __forceinline__ float bf_round(float x) {
    return __bfloat162float(__float2bfloat16_rn(x));
}
__device__ __forceinline__ uint32_t h2_pack(float a, float b) {
    __half2 t = __floats2half2_rn(a, b);
    return *reinterpret_cast<uint32_t*>(&t);
}

__device__ __forceinline__ int load_idx(const void* p, int i, int is64) {
    if (is64) return (int)((const long long*)p)[i];
    return ((const int*)p)[i];
}

// ---------------- merged prep: weight splits + rowptr (+ idx detection) -----
#define WPREP_ITEMS (IN_F * HID + HID * OUT_F)     // 147456
#define WPREP_BLKS  ((WPREP_ITEMS + 255) / 256)    // 576
#define RPTR_BLKS   ((NN + 1 + 255) / 256)         // 196

__device__ __forceinline__ int detect_is64(const void* a_col_raw, int E) {
    const long long* p = (const long long*)a_col_raw;
    int ok = 1;
    #pragma unroll 4
    for (int i = 0; i < 16; i++) {
        long long v = p[i];
        if (v < 0 || v >= NN) { ok = 0; break; }
    }
    if (ok) {
        #pragma unroll 4
        for (int i = 0; i < 16; i++) {
            long long v = p[E / 2 + i];
            if (v < 0 || v >= NN) { ok = 0; break; }
        }
    }
    return ok;
}

__global__ void prep_all_kernel(const float* __restrict__ W1,
                                const float* __restrict__ W2,
                                const void* __restrict__ a_row,
                                const void* __restrict__ a_col,
                                int E) {
    int b = blockIdx.x;
    if (b < WPREP_BLKS) {
        int idx = b * 256 + threadIdx.x;
        if (idx < IN_F * HID) {
            int n = idx >> 9, k = idx & 511;
            float v = W1[(size_t)k * HID + n];
            __nv_bfloat16 h = __float2bfloat16_rn(v);
            g_w1t_hi[idx] = h;
            g_w1t_lo[idx] = __float2bfloat16_rn(v - __bfloat162float(h));
        } else {
            int j = idx - IN_F * HID;
            if (j < HID * OUT_F) {
                int n = j >> 8, k = j & 255;
                float v = W2[(size_t)k * OUT_F + n];
                __nv_bfloat16 h = __float2bfloat16_rn(v);
                g_w2t_hi[j] = h;
                g_w2t_lo[j] = __float2bfloat16_rn(v - __bfloat162float(h));
            }
        }
    } else {
        int is64 = detect_is64(a_col, E);
        int r = (b - WPREP_BLKS) * 256 + threadIdx.x;
        if (b == WPREP_BLKS && threadIdx.x == 0) g_is64 = is64;
        if (r > NN) return;
        if (r == NN) { g_rowptr[NN] = E; return; }
        int lo = 0, hi = E;
        while (lo < hi) {
            int mid = (lo + hi) >> 1;
            if (load_idx(a_row, mid, is64) < r) lo = mid + 1; else hi = mid;
        }
        g_rowptr[r] = lo;
    }
}

// ---------------- GEMM1: X@W1 CTA 128x128, bf16 3-term, reg-staged X --------
// (R11/R13 proven config: 80KB smem -> 2 CTAs/SM, 256 thr, 2 syncs/k-chunk)
#define ROWB   80
#define G1_AHI 0          // 2 x 10240
#define G1_ALO 20480
#define G1_BHI 40960
#define G1_BLO 61440
#define G1_TOTAL 81920

__global__ void __launch_bounds__(256, 2)
gemm1_mma_kernel(const float* __restrict__ X, __half* __restrict__ outh) {
    extern __shared__ char smem[];
    const uint32_t sm0 = smem_u32(smem);
    const int tid = threadIdx.x;
    const int wid = tid >> 5, lane = tid & 31;
    const int warp_m = wid & 3, warp_n = wid >> 2;
    const int colBase = blockIdx.x * 128;   // 0 or 128 (HID)
    const int rowBase = blockIdx.y * 128;

    float acc[2][8][4];
    #pragma unroll
    for (int i = 0; i < 2; i++)
        #pragma unroll
        for (int j = 0; j < 8; j++)
            #pragma unroll
            for (int t = 0; t < 4; t++) acc[i][j][t] = 0.f;

    const int xrow = tid >> 3;   // 0..31 (+32i)
    const int xq   = tid & 7;    // 16B chunk in 128B row
    float4 xr[4];

    auto ldg_x = [&](int kc) {
        int k0 = kc * 32;
        #pragma unroll
        for (int i = 0; i < 4; i++) {
            int rg = rowBase + xrow + 32 * i;
            if (rg >= NN) rg = NN - 1;
            xr[i] = __ldg((const float4*)(X + (size_t)rg * IN_F + k0 + xq * 4));
        }
    };
    auto convert_x = [&](int s) {
        char* ah = smem + G1_AHI + s * 10240;
        char* al = smem + G1_ALO + s * 10240;
        #pragma unroll
        for (int i = 0; i < 4; i++) {
            int row = xrow + 32 * i;
            float4 v = xr[i];
            float h0 = bf_round(v.x), h1 = bf_round(v.y);
            float h2 = bf_round(v.z), h3 = bf_round(v.w);
            uint2 hi = make_uint2(bf2_pack(v.x, v.y), bf2_pack(v.z, v.w));
            uint2 lo = make_uint2(bf2_pack(v.x - h0, v.y - h1),
                                  bf2_pack(v.z - h2, v.w - h3));
            *(uint2*)(ah + row * ROWB + xq * 8) = hi;
            *(uint2*)(al + row * ROWB + xq * 8) = lo;
        }
    };
    auto load_b = [&](int s, int kc) {
        int k0 = kc * 32;
        uint32_t bh = sm0 + G1_BHI + s * 10240;
        uint32_t bl = sm0 + G1_BLO + s * 10240;
        #pragma unroll
        for (int i = 0; i < 2; i++) {
            int c = tid + 256 * i;          // 0..511 : 128 B-rows x 4 chunks
            int row = c >> 2, q = c & 3;
            uint32_t o = row * ROWB + q * 16;
            cpa16(bh + o, g_w1t_hi + (size_t)(colBase + row) * IN_F + k0 + q * 8);
            cpa16(bl + o, g_w1t_lo + (size_t)(colBase + row) * IN_F + k0 + q * 8);
        }
    };

    const int lq = lane >> 3, lr = lane & 7;

    auto compute_stage = [&](int s) {
        uint32_t ah = sm0 + G1_AHI + s * 10240;
        uint32_t al = sm0 + G1_ALO + s * 10240;
        uint32_t bhb = sm0 + G1_BHI + s * 10240;
        uint32_t blb = sm0 + G1_BLO + s * 10240;
        #pragma unroll
        for (int ks = 0; ks < 2; ks++) {
            uint32_t ahi[2][4], alo[2][4];
            #pragma unroll
            for (int mb = 0; mb < 2; mb++) {
                int row = warp_m * 32 + mb * 16 + (lq & 1) * 8 + lr;
                int kb  = ks * 32 + (lq >> 1) * 16;
                ldsm_x4(ahi[mb][0], ahi[mb][1], ahi[mb][2], ahi[mb][3],
                        ah + row * ROWB + kb);
                ldsm_x4(alo[mb][0], alo[mb][1], alo[mb][2], alo[mb][3],
                        al + row * ROWB + kb);
            }
            #pragma unroll
            for (int g = 0; g < 4; g++) {
                int row = warp_n * 64 + g * 16 + (lq >> 1) * 8 + lr;
                int kb  = ks * 32 + (lq & 1) * 16;
                uint32_t o = row * ROWB + kb;
                uint32_t bh0, bh1, bh2, bh3, bl0, bl1, bl2, bl3;
                ldsm_x4(bh0, bh1, bh2, bh3, bhb + o);
                ldsm_x4(bl0, bl1, bl2, bl3, blb + o);
                #pragma unroll
                for (int mb = 0; mb < 2; mb++) {
                    mma_bf16_2(acc[mb][2*g],   ahi[mb], bh0, bh1);
                    mma_bf16_2(acc[mb][2*g],   ahi[mb], bl0, bl1);
                    mma_bf16_2(acc[mb][2*g],   alo[mb], bh0, bh1);
                    mma_bf16_2(acc[mb][2*g+1], ahi[mb], bh2, bh3);
                    mma_bf16_2(acc[mb][2*g+1], ahi[mb], bl2, bl3);
                    mma_bf16_2(acc[mb][2*g+1], alo[mb], bh2, bh3);
                }
            }
        }
    };

    load_b(0, 0); CP_COMMIT();
    ldg_x(0);
    for (int kc = 0; kc < 16; kc++) {
        if (kc < 15) { load_b((kc + 1) & 1, kc + 1); CP_COMMIT(); }
        convert_x(kc & 1);
        if (kc < 15) ldg_x(kc + 1);
        if (kc < 15) CP_WAIT_1(); else CP_WAIT_0();
        __syncthreads();
        compute_stage(kc & 1);
        __syncthreads();
    }

    const int gid = lane >> 2, tg = lane & 3;
    #pragma unroll
    for (int mb = 0; mb < 2; mb++) {
        int r0 = rowBase + warp_m * 32 + mb * 16 + gid;
        int r1 = r0 + 8;
        #pragma unroll
        for (int nb = 0; nb < 8; nb++) {
            int col = colBase + warp_n * 64 + nb * 8 + tg * 2;
            if (r0 < NN)
                *(__half2*)&outh[(size_t)r0 * HID + col] =
                    __floats2half2_rn(acc[mb][nb][0], acc[mb][nb][1]);
            if (r1 < NN)
                *(__half2*)&outh[(size_t)r1 * HID + col] =
                    __floats2half2_rn(acc[mb][nb][2], acc[mb][nb][3]);
        }
    }
}

// ---------------- GEMM2: 3-stage circular pipeline, 1 sync per k-chunk ------
#define S2_A_HI 0
#define S2_A_LO 10240
#define S2_B_HI 20480
#define S2_B_LO 25600
#define STG2    30720
#define G2_TOTAL (3 * STG2)   // 92160 -> still 2 CTAs/SM

__global__ void __launch_bounds__(256, 2)
gemm2_mma_kernel(__half* __restrict__ outh) {
    extern __shared__ char smem[];
    const uint32_t sm0 = smem_u32(smem);
    const int tid = threadIdx.x;
    const int wid = tid >> 5, lane = tid & 31;
    const int warp_m = wid & 3, warp_n = wid >> 2;
    const int rowBase = blockIdx.x * 128;

    float acc[2][4][4];
    #pragma unroll
    for (int i = 0; i < 2; i++)
        #pragma unroll
        for (int j = 0; j < 4; j++)
            #pragma unroll
            for (int t = 0; t < 4; t++) acc[i][j][t] = 0.f;

    auto load_stage = [&](int s, int kc) {
        int k0 = kc * 32;
        uint32_t sb = sm0 + s * STG2;
        #pragma unroll
        for (int i = 0; i < 2; i++) {
            int c = tid + 256 * i;
            int row = c >> 2, q = c & 3;
            int rg = rowBase + row; if (rg >= NN) rg = NN - 1;
            uint32_t o = row * ROWB + q * 16;
            cpa16(sb + S2_A_HI + o, g_h_hi + (size_t)rg * HID + k0 + q * 8);
            cpa16(sb + S2_A_LO + o, g_h_lo + (size_t)rg * HID + k0 + q * 8);
        }
        {
            int row = tid >> 2, q = tid & 3;
            uint32_t o = row * ROWB + q * 16;
            cpa16(sb + S2_B_HI + o, g_w2t_hi + (size_t)row * HID + k0 + q * 8);
            cpa16(sb + S2_B_LO + o, g_w2t_lo + (size_t)row * HID + k0 + q * 8);
        }
    };

    const int lq = lane >> 3, lr = lane & 7;

    auto compute_stage = [&](int s) {
        uint32_t sb = sm0 + s * STG2;
        #pragma unroll
        for (int ks = 0; ks < 2; ks++) {
            uint32_t ahi[2][4], alo[2][4];
            #pragma unroll
            for (int mb = 0; mb < 2; mb++) {
                int row = warp_m * 32 + mb * 16 + (lq & 1) * 8 + lr;
                int kb  = ks * 32 + (lq >> 1) * 16;
                uint32_t o = row * ROWB + kb;
                ldsm_x4(ahi[mb][0], ahi[mb][1], ahi[mb][2], ahi[mb][3], sb + S2_A_HI + o);
                ldsm_x4(alo[mb][0], alo[mb][1], alo[mb][2], alo[mb][3], sb + S2_A_LO + o);
            }
            #pragma unroll
            for (int g = 0; g < 2; g++) {
                int row = warp_n * 32 + g * 16 + (lq >> 1) * 8 + lr;
                int kb  = ks * 32 + (lq & 1) * 16;
                uint32_t o = row * ROWB + kb;
                uint32_t bh0, bh1, bh2, bh3, bl0, bl1, bl2, bl3;
                ldsm_x4(bh0, bh1, bh2, bh3, sb + S2_B_HI + o);
                ldsm_x4(bl0, bl1, bl2, bl3, sb + S2_B_LO + o);
                #pragma unroll
                for (int mb = 0; mb < 2; mb++) {
                    mma_bf16_2(acc[mb][2*g],   ahi[mb], bh0, bh1);
                    mma_bf16_2(acc[mb][2*g],   ahi[mb], bl0, bl1);
                    mma_bf16_2(acc[mb][2*g],   alo[mb], bh0, bh1);
                    mma_bf16_2(acc[mb][2*g+1], ahi[mb], bh2, bh3);
                    mma_bf16_2(acc[mb][2*g+1], ahi[mb], bl2, bl3);
                    mma_bf16_2(acc[mb][2*g+1], alo[mb], bh2, bh3);
                }
            }
        }
    };

    // prologue: stages 0,1 in flight
    load_stage(0, 0); CP_COMMIT();
    load_stage(1, 1); CP_COMMIT();

    for (int kc = 0; kc < 8; kc++) {
        if (kc < 7) CP_WAIT_1(); else CP_WAIT_0();
        __syncthreads();                    // stage kc visible to all
        compute_stage(kc % 3);
        if (kc + 2 < 8) {                   // write buffer (kc+2)%3 != kc%3:
            load_stage((kc + 2) % 3, kc + 2); // all warps past sync(kc) =>
            CP_COMMIT();                    // compute(kc-1) globally done. Safe.
        }
    }

    const int gid = lane >> 2, tg = lane & 3;
    #pragma unroll
    for (int mb = 0; mb < 2; mb++) {
        int r0 = rowBase + warp_m * 32 + mb * 16 + gid;
        int r1 = r0 + 8;
        #pragma unroll
        for (int nb = 0; nb < 4; nb++) {
            int col = warp_n * 32 + nb * 8 + tg * 2;
            if (r0 < NN)
                *(__half2*)&outh[(size_t)r0 * OUT_F + col] =
                    __floats2half2_rn(acc[mb][nb][0], acc[mb][nb][1]);
            if (r1 < NN)
                *(__half2*)&outh[(size_t)r1 * OUT_F + col] =
                    __floats2half2_rn(acc[mb][nb][2], acc[mb][nb][3]);
        }
    }
}

// ---------------- SpMM1 (+ ReLU + dropout + bf16 split) : warp per row ------
__global__ void __launch_bounds__(256)
spmm1_kernel(const void* __restrict__ a_col,
             const float* __restrict__ a_val,
             const int* __restrict__ drop_mask) {
    int warp = (blockIdx.x * blockDim.x + threadIdx.x) >> 5;
    int lane = threadIdx.x & 31;
    if (warp >= NN) return;
    const int is64 = g_is64;
    int e0 = g_rowptr[warp];
    int e1 = g_rowptr[warp + 1];

    float acc[8];
    #pragma unroll
    for (int j = 0; j < 8; j++) acc[j] = 0.f;

    int e = e0;
    for (; e + 7 < e1; e += 8) {
        int cc[8]; float vv[8]; uint4 q[8];
        #pragma unroll
        for (int j = 0; j < 8; j++) {
            cc[j] = load_idx(a_col, e + j, is64);
            vv[j] = __ldg(&a_val[e + j]);
        }
        #pragma unroll
        for (int j = 0; j < 8; j++)
            q[j] = __ldg((const uint4*)(g_xw1h + (size_t)cc[j] * HID) + lane);
        #pragma unroll
        for (int j = 0; j < 8; j++) {
            float2 f0 = __half22float2(*reinterpret_cast<__half2*>(&q[j].x));
            float2 f1 = __half22float2(*reinterpret_cast<__half2*>(&q[j].y));
            float2 f2 = __half22float2(*reinterpret_cast<__half2*>(&q[j].z));
            float2 f3 = __half22float2(*reinterpret_cast<__half2*>(&q[j].w));
            acc[0] = fmaf(vv[j], f0.x, acc[0]); acc[1] = fmaf(vv[j], f0.y, acc[1]);
            acc[2] = fmaf(vv[j], f1.x, acc[2]); acc[3] = fmaf(vv[j], f1.y, acc[3]);
            acc[4] = fmaf(vv[j], f2.x, acc[4]); acc[5] = fmaf(vv[j], f2.y, acc[5]);
            acc[6] = fmaf(vv[j], f3.x, acc[6]); acc[7] = fmaf(vv[j], f3.y, acc[7]);
        }
    }
    for (; e + 3 < e1; e += 4) {
        int cc[4]; float vv[4]; uint4 q[4];
        #pragma unroll
        for (int j = 0; j < 4; j++) {
            cc[j] = load_idx(a_col, e + j, is64);
            vv[j] = __ldg(&a_val[e + j]);
        }
        #pragma unroll
        for (int j = 0; j < 4; j++)
            q[j] = __ldg((const uint4*)(g_xw1h + (size_t)cc[j] * HID) + lane);
        #pragma unroll
        for (int j = 0; j < 4; j++) {
            float2 f0 = __half22float2(*reinterpret_cast<__half2*>(&q[j].x));
            float2 f1 = __half22float2(*reinterpret_cast<__half2*>(&q[j].y));
            float2 f2 = __half22float2(*reinterpret_cast<__half2*>(&q[j].z));
            float2 f3 = __half22float2(*reinterpret_cast<__half2*>(&q[j].w));
            acc[0] = fmaf(vv[j], f0.x, acc[0]); acc[1] = fmaf(vv[j], f0.y, acc[1]);
            acc[2] = fmaf(vv[j], f1.x, acc[2]); acc[3] = fmaf(vv[j], f1.y, acc[3]);
            acc[4] = fmaf(vv[j], f2.x, acc[4]); acc[5] = fmaf(vv[j], f2.y, acc[5]);
            acc[6] = fmaf(vv[j], f3.x, acc[6]); acc[7] = fmaf(vv[j], f3.y, acc[7]);
        }
    }
    for (; e < e1; e++) {
        int   col = load_idx(a_col, e, is64);
        float v   = __ldg(&a_val[e]);
        uint4 q = __ldg((const uint4*)(g_xw1h + (size_t)col * HID) + lane);
        float2 f0 = __half22float2(*reinterpret_cast<__half2*>(&q.x));
        float2 f1 = __half22float2(*reinterpret_cast<__half2*>(&q.y));
        float2 f2 = __half22float2(*reinterpret_cast<__half2*>(&q.z));
        float2 f3 = __half22float2(*reinterpret_cast<__half2*>(&q.w));
        acc[0] = fmaf(v, f0.x, acc[0]); acc[1] = fmaf(v, f0.y, acc[1]);
        acc[2] = fmaf(v, f1.x, acc[2]); acc[3] = fmaf(v, f1.y, acc[3]);
        acc[4] = fmaf(v, f2.x, acc[4]); acc[5] = fmaf(v, f2.y, acc[5]);
        acc[6] = fmaf(v, f3.x, acc[6]); acc[7] = fmaf(v, f3.y, acc[7]);
    }

    const int4* mrow = (const int4*)(drop_mask + (size_t)warp * HID) + lane * 2;
    int4 m0 = __ldg(mrow);
    int4 m1 = __ldg(mrow + 1);

    float r[8];
    r[0] = fmaxf(acc[0], 0.f) * (float)m0.x * 2.0f;
    r[1] = fmaxf(acc[1], 0.f) * (float)m0.y * 2.0f;
    r[2] = fmaxf(acc[2], 0.f) * (float)m0.z * 2.0f;
    r[3] = fmaxf(acc[3], 0.f) * (float)m0.w * 2.0f;
    r[4] = fmaxf(acc[4], 0.f) * (float)m1.x * 2.0f;
    r[5] = fmaxf(acc[5], 0.f) * (float)m1.y * 2.0f;
    r[6] = fmaxf(acc[6], 0.f) * (float)m1.z * 2.0f;
    r[7] = fmaxf(acc[7], 0.f) * (float)m1.w * 2.0f;

    uint4 hi, lo;
    float h0, h1;
    h0 = bf_round(r[0]); h1 = bf_round(r[1]);
    hi.x = bf2_pack(r[0], r[1]); lo.x = bf2_pack(r[0] - h0, r[1] - h1);
    h0 = bf_round(r[2]); h1 = bf_round(r[3]);
    hi.y = bf2_pack(r[2], r[3]); lo.y = bf2_pack(r[2] - h0, r[3] - h1);
    h0 = bf_round(r[4]); h1 = bf_round(r[5]);
    hi.z = bf2_pack(r[4], r[5]); lo.z = bf2_pack(r[4] - h0, r[5] - h1);
    h0 = bf_round(r[6]); h1 = bf_round(r[7]);
    hi.w = bf2_pack(r[6], r[7]); lo.w = bf2_pack(r[6] - h0, r[7] - h1);

    *(uint4*)(g_h_hi + (size_t)warp * HID + lane * 8) = hi;
    *(uint4*)(g_h_lo + (size_t)warp * HID + lane * 8) = lo;
}

// ---------------- SpMM2 + log_softmax : warp per row (fp16 gather) ----------
__global__ void __launch_bounds__(256)
spmm2_lsm_kernel(const void* __restrict__ a_col,
                 const float* __restrict__ a_val,
                 float* __restrict__ out) {
    int warp = (blockIdx.x * blockDim.x + threadIdx.x) >> 5;
    int lane = threadIdx.x & 31;
    if (warp >= NN) return;
    const int is64 = g_is64;
    int e0 = g_rowptr[warp];
    int e1 = g_rowptr[warp + 1];

    float a0 = 0.f, a1 = 0.f;
    int e = e0;
    for (; e + 7 < e1; e += 8) {
        int cc[8]; float vv[8]; uint32_t u[8];
        #pragma unroll
        for (int j = 0; j < 8; j++) {
            cc[j] = load_idx(a_col, e + j, is64);
            vv[j] = __ldg(&a_val[e + j]);
        }
        #pragma unroll
        for (int j = 0; j < 8; j++)
            u[j] = __ldg((const uint32_t*)(g_hw2h + (size_t)cc[j] * OUT_F) + lane);
        #pragma unroll
        for (int j = 0; j < 8; j++) {
            float2 f = __half22float2(*reinterpret_cast<__half2*>(&u[j]));
            a0 = fmaf(vv[j], f.x, a0);
            a1 = fmaf(vv[j], f.y, a1);
        }
    }
    for (; e < e1; e++) {
        int   col = load_idx(a_col, e, is64);
        float v   = __ldg(&a_val[e]);
        uint32_t u = __ldg((const uint32_t*)(g_hw2h + (size_t)col * OUT_F) + lane);
        float2 f = __half22float2(*reinterpret_cast<__half2*>(&u));
        a0 = fmaf(v, f.x, a0);
        a1 = fmaf(v, f.y, a1);
    }

    float m = fmaxf(a0, a1);
    #pragma unroll
    for (int off = 16; off > 0; off >>= 1)
        m = fmaxf(m, __shfl_xor_sync(0xFFFFFFFFu, m, off));
    float s = expf(a0 - m) + expf(a1 - m);
    #pragma unroll
    for (int off = 16; off > 0; off >>= 1)
        s += __shfl_xor_sync(0xFFFFFFFFu, s, off);
    float ls = logf(s) + m;

    out[(size_t)warp * OUT_F + lane * 2]     = a0 - ls;
    out[(size_t)warp * OUT_F + lane * 2 + 1] = a1 - ls;
}

// ---------------- launch ----------------------------------------------------
extern "C" void kernel_launch(void* const* d_in, const int* in_sizes, int n_in,
                              void* d_out, int out_size) {
    const float* X     = (const float*)d_in[0];
    const float* W1    = (const float*)d_in[1];
    const float* W2    = (const float*)d_in[2];
    const void*  a_row = d_in[3];
    const void*  a_col = d_in[4];
    const float* a_val = (const float*)d_in[5];
    const int*   dmask = (const int*)d_in[6];
    float*       out   = (float*)d_out;

    const int E = in_sizes[5];

    __half *p_xw1h, *p_hw2h;
    cudaGetSymbolAddress((void**)&p_xw1h, g_xw1h);
    cudaGetSymbolAddress((void**)&p_hw2h, g_hw2h);

    static int smem_set = 0;
    if (!smem_set) {
        cudaFuncSetAttribute(gemm1_mma_kernel,
                             cudaFuncAttributeMaxDynamicSharedMemorySize, G1_TOTAL);
        cudaFuncSetAttribute(gemm2_mma_kernel,
                             cudaFuncAttributeMaxDynamicSharedMemorySize, G2_TOTAL);
        smem_set = 1;
    }

    // idx0: merged prep (W splits + rowptr + idx-dtype detection)
    prep_all_kernel<<<WPREP_BLKS + RPTR_BLKS, 256>>>(W1, W2, a_row, a_col, E);

    // idx1: GEMM1 xw1 = X @ W1 -> fp16
    {
        dim3 grid(HID / 128, (NN + 127) / 128);
        gemm1_mma_kernel<<<grid, 256, G1_TOTAL>>>(X, p_xw1h);
    }

    // idx2: SpMM1 + relu + dropout -> h (bf16 hi/lo)
    spmm1_kernel<<<(NN * 32 + 255) / 256, 256>>>(a_col, a_val, dmask);

    // idx3: GEMM2 hw2 = h @ W2 -> fp16 (3-stage, 1 sync/chunk)
    gemm2_mma_kernel<<<(NN + 127) / 128, 256, G2_TOTAL>>>(p_hw2h);

    // idx4: SpMM2 + log_softmax -> out
    spmm2_lsm_kernel<<<(NN * 32 + 255) / 256, 256>>>(a_col, a_val, out);
}